// round 14
// baseline (speedup 1.0000x reference)
#include <cuda_runtime.h>
#include <math_constants.h>
#include <cstdint>

#define H_IN   256
#define W_IN   256
#define H_OUT  128
#define W_OUT  128
#define NEG_INF (-CUDART_INF_F)

// Per-warp smem ring: 8 row slots x 256 floats (1KB) = 8KB/warp, 32KB/CTA.
// Slot for (local) input row r is r & 7. Lane l owns bytes [l*32, l*32+32).
#define SLOT_F   256
#define WARP_F   (8 * SLOT_F)

struct Row8 { float4 a, b; };

__device__ __forceinline__ void cp16(uint32_t dst, const float* src) {
    asm volatile("cp.async.cg.shared.global [%0], [%1], 16;"
                 :: "r"(dst), "l"(src) : "memory");
}
__device__ __forceinline__ void cp_commit() {
    asm volatile("cp.async.commit_group;" ::: "memory");
}
template<int N>
__device__ __forceinline__ void cp_wait() {
    asm volatile("cp.async.wait_group %0;" :: "n"(N) : "memory");
}

// Stage (local) row r into its slot; fpr = plane base + strip row offset.
__device__ __forceinline__ void stage(uint32_t wsm32, int lane,
                                      const float* __restrict__ fpr, int r) {
    const float* rp = fpr + r * W_IN + 8 * lane;
    uint32_t d = wsm32 + (uint32_t)((r & 7) * SLOT_F * 4 + lane * 32);
    cp16(d,      rp);
    cp16(d + 16, rp + 4);
}

// Guarded stage: OOB rows get -inf via direct STS (synchronous, own data).
__device__ __forceinline__ void stage_g(uint32_t wsm32, float* wsm, int lane,
                                        const float* __restrict__ fpr,
                                        int r, int g) {
    if ((unsigned)g < (unsigned)H_IN) {
        stage(wsm32, lane, fpr, r);
    } else {
        float4 ninf = make_float4(NEG_INF, NEG_INF, NEG_INF, NEG_INF);
        float4* q = (float4*)(wsm + (r & 7) * SLOT_F + lane * 8);
        q[0] = ninf; q[1] = ninf;
    }
}

// Read back this lane's 32B of a staged row.
__device__ __forceinline__ Row8 lrow(const float* wsm, int lane, int s) {
    const float4* q = (const float4*)(wsm + s * SLOT_F + lane * 8);
    Row8 x; x.a = q[0]; x.b = q[1]; return x;
}

// Horizontal 7-tap max-plus (symmetric weights): 4 output cols per lane.
__device__ __forceinline__ float4 hmax(const Row8& x, int lane,
                                       float h1, float h2, float h3)
{
    float m3 = __shfl_up_sync(0xffffffffu, x.b.y, 1);   // col 8l-3
    float m2 = __shfl_up_sync(0xffffffffu, x.b.z, 1);   // col 8l-2
    float m1 = __shfl_up_sync(0xffffffffu, x.b.w, 1);   // col 8l-1
    float p8 = __shfl_down_sync(0xffffffffu, x.a.x, 1); // col 8l+8
    float p9 = __shfl_down_sync(0xffffffffu, x.a.y, 1); // col 8l+9
    if (lane == 0)  { m3 = NEG_INF; m2 = NEG_INF; m1 = NEG_INF; }
    if (lane == 31) { p8 = NEG_INF; p9 = NEG_INF; }

    float4 g;
    g.x = fmaxf(fmaxf(x.a.x,                    fmaxf(m1,    x.a.y) + h1),
                fmaxf(fmaxf(m2,    x.a.z) + h2, fmaxf(m3,    x.a.w) + h3));
    g.y = fmaxf(fmaxf(x.a.z,                    fmaxf(x.a.y, x.a.w) + h1),
                fmaxf(fmaxf(x.a.x, x.b.x) + h2, fmaxf(m1,    x.b.y) + h3));
    g.z = fmaxf(fmaxf(x.b.x,                    fmaxf(x.a.w, x.b.y) + h1),
                fmaxf(fmaxf(x.a.z, x.b.z) + h2, fmaxf(x.a.y, x.b.w) + h3));
    g.w = fmaxf(fmaxf(x.b.z,                    fmaxf(x.b.y, x.b.w) + h1),
                fmaxf(fmaxf(x.b.x, p8)    + h2, fmaxf(x.a.w, p9)    + h3));
    return g;
}

__device__ __forceinline__ float4 vmax(const float4* ring, int s0,
                                       float h1, float h2, float h3)
{
    float4 c  = ring[s0 & 7];
    float4 a1 = ring[(s0 + 7) & 7], b1 = ring[(s0 + 1) & 7];
    float4 a2 = ring[(s0 + 6) & 7], b2 = ring[(s0 + 2) & 7];
    float4 a3 = ring[(s0 + 5) & 7], b3 = ring[(s0 + 3) & 7];
    float4 o;
    o.x = fmaxf(fmaxf(c.x, fmaxf(a1.x, b1.x) + h1),
                fmaxf(fmaxf(a2.x, b2.x) + h2, fmaxf(a3.x, b3.x) + h3));
    o.y = fmaxf(fmaxf(c.y, fmaxf(a1.y, b1.y) + h1),
                fmaxf(fmaxf(a2.y, b2.y) + h2, fmaxf(a3.y, b3.y) + h3));
    o.z = fmaxf(fmaxf(c.z, fmaxf(a1.z, b1.z) + h1),
                fmaxf(fmaxf(a2.z, b2.z) + h2, fmaxf(a3.z, b3.z) + h3));
    o.w = fmaxf(fmaxf(c.w, fmaxf(a1.w, b1.w) + h1),
                fmaxf(fmaxf(a2.w, b2.w) + h2, fmaxf(a3.w, b3.w) + h3));
    return o;
}

__global__ __launch_bounds__(128)
void parabolic_pool_kernel(const float* __restrict__ f,
                           const float* __restrict__ tptr,
                           float* __restrict__ out)
{
    __shared__ __align__(16) float sbuf[4 * WARP_F];   // 32 KB

    const int wid   = threadIdx.x >> 5;
    const int lane  = threadIdx.x & 31;
    const int gw    = blockIdx.x * 4 + wid;            // 0..4095
    const int plane = gw >> 1;
    const int i0    = (gw & 1) * 64;                   // output strip origin
    const int r0    = 2 * i0;                          // input row base

    float* wsm = &sbuf[wid * WARP_F];
    uint32_t wsm32 = (uint32_t)__cvta_generic_to_shared(wsm);

    // fpr: local row r -> global row r0 + r
    const float* __restrict__ fpr = f + (size_t)plane * (H_IN * W_IN)
                                      + (size_t)r0 * W_IN;
    float* __restrict__ op = out + (size_t)plane * (H_OUT * W_OUT)
                                 + (size_t)i0 * W_OUT + 4 * lane;

    const float inv4t = 0.25f / tptr[0];
    const float h1 = -1.0f * inv4t;
    const float h2 = -4.0f * inv4t;
    const float h3 = -9.0f * inv4t;

    float4 ring[8];   // ring[r & 7] = hmax of local input row r

    // ---- prologue: stage local rows -3..3 (guarded at top edge), one group ----
#pragma unroll
    for (int k = 0; k < 7; ++k) {
        const int r = k - 3;
        stage_g(wsm32, wsm, lane, fpr, r, r0 + r);
    }
    cp_commit();
    cp_wait<0>();
#pragma unroll
    for (int k = 0; k < 7; ++k) {
        const int r = k - 3;
        ring[r & 7] = hmax(lrow(wsm, lane, r & 7), lane, h1, h2, h3);
    }

    // prime 3 pairs in flight: rows (4,5), (6,7), (8,9) -- always in range
    stage(wsm32, lane, fpr, 4); stage(wsm32, lane, fpr, 5); cp_commit();
    stage(wsm32, lane, fpr, 6); stage(wsm32, lane, fpr, 7); cp_commit();
    stage(wsm32, lane, fpr, 8); stage(wsm32, lane, fpr, 9); cp_commit();

    // ---- body macro-step: commit (2i+10,2i+11); vmax+store i; wait; hmax (2i+4,2i+5)
#define BODY_STEP(i, ip)                                                      \
    {                                                                         \
        stage(wsm32, lane, fpr, 2*(i) + 10);                                  \
        stage(wsm32, lane, fpr, 2*(i) + 11);                                  \
        cp_commit();                                                          \
        float4 o = vmax(ring, (2*(ip)) & 7, h1, h2, h3);                      \
        __stcs((float4*)(op + (i) * W_OUT), o);                               \
        cp_wait<3>();                                                         \
        ring[(2*(ip)+4) & 7] = hmax(lrow(wsm, lane, (2*(ip)+4) & 7),          \
                                    lane, h1, h2, h3);                        \
        ring[(2*(ip)+5) & 7] = hmax(lrow(wsm, lane, (2*(ip)+5) & 7),          \
                                    lane, h1, h2, h3);                        \
    }

    // main loop: i = 0..55 (rows staged <= 121, always in range)
    for (int ib = 0; ib < 14; ++ib) {
#pragma unroll
        for (int ip = 0; ip < 4; ++ip) {
            const int i = ib * 4 + ip;
            BODY_STEP(i, ip);
        }
    }
    // i = 56..58: rows staged 122..127, in range for both strips
    BODY_STEP(56, 0);
    BODY_STEP(57, 1);
    BODY_STEP(58, 2);

    // i = 59: stage rows 128,129 (OOB for upper strip -> -inf via STS)
    {
        stage_g(wsm32, wsm, lane, fpr, 128, r0 + 128);
        stage_g(wsm32, wsm, lane, fpr, 129, r0 + 129);
        cp_commit();
        float4 o = vmax(ring, 6, h1, h2, h3);
        __stcs((float4*)(op + 59 * W_OUT), o);
        cp_wait<3>();
        ring[2] = hmax(lrow(wsm, lane, 2), lane, h1, h2, h3);   // row 122
        ring[3] = hmax(lrow(wsm, lane, 3), lane, h1, h2, h3);   // row 123
    }
    // i = 60..63: drain (no new commits)
    {
        float4 o = vmax(ring, 0, h1, h2, h3);
        __stcs((float4*)(op + 60 * W_OUT), o);
        cp_wait<2>();
        ring[4] = hmax(lrow(wsm, lane, 4), lane, h1, h2, h3);   // row 124
        ring[5] = hmax(lrow(wsm, lane, 5), lane, h1, h2, h3);   // row 125
    }
    {
        float4 o = vmax(ring, 2, h1, h2, h3);
        __stcs((float4*)(op + 61 * W_OUT), o);
        cp_wait<1>();
        ring[6] = hmax(lrow(wsm, lane, 6), lane, h1, h2, h3);   // row 126
        ring[7] = hmax(lrow(wsm, lane, 7), lane, h1, h2, h3);   // row 127
    }
    {
        float4 o = vmax(ring, 4, h1, h2, h3);
        __stcs((float4*)(op + 62 * W_OUT), o);
        cp_wait<0>();
        ring[0] = hmax(lrow(wsm, lane, 0), lane, h1, h2, h3);   // row 128
        ring[1] = hmax(lrow(wsm, lane, 1), lane, h1, h2, h3);   // row 129
    }
    {
        float4 o = vmax(ring, 6, h1, h2, h3);
        __stcs((float4*)(op + 63 * W_OUT), o);
    }
#undef BODY_STEP
}

extern "C" void kernel_launch(void* const* d_in, const int* in_sizes, int n_in,
                              void* d_out, int out_size)
{
    const float* f = (const float*)d_in[0];
    const float* t = (const float*)d_in[1];
    float* out = (float*)d_out;

    // 2048 planes x 2 row-strips = 4096 warps = 1024 blocks x 4 warps
    parabolic_pool_kernel<<<1024, 128>>>(f, t, out);
}

// round 15
// speedup vs baseline: 1.0006x; 1.0006x over previous
#include <cuda_runtime.h>
#include <math_constants.h>
#include <cstdint>

#define H_IN   256
#define W_IN   256
#define H_OUT  128
#define W_OUT  128
#define NEG_INF (-CUDART_INF_F)

// Per-warp smem ring: 8 row slots x 256 floats (1KB) = 8KB/warp.
// 2 warps/CTA -> 16KB/CTA -> 13 CTAs/SM (smem & regs) = 26 warps/SM.
// Slot for (local) input row r is r & 7. Lane l owns bytes [l*32, l*32+32).
#define SLOT_F   256
#define WARP_F   (8 * SLOT_F)
#define WARPS_PER_CTA 2

struct Row8 { float4 a, b; };

__device__ __forceinline__ void cp16(uint32_t dst, const float* src) {
    asm volatile("cp.async.cg.shared.global [%0], [%1], 16;"
                 :: "r"(dst), "l"(src) : "memory");
}
__device__ __forceinline__ void cp_commit() {
    asm volatile("cp.async.commit_group;" ::: "memory");
}
template<int N>
__device__ __forceinline__ void cp_wait() {
    asm volatile("cp.async.wait_group %0;" :: "n"(N) : "memory");
}

// Stage (local) row r into its slot; fpr = plane base + strip row offset.
__device__ __forceinline__ void stage(uint32_t wsm32, int lane,
                                      const float* __restrict__ fpr, int r) {
    const float* rp = fpr + r * W_IN + 8 * lane;
    uint32_t d = wsm32 + (uint32_t)((r & 7) * SLOT_F * 4 + lane * 32);
    cp16(d,      rp);
    cp16(d + 16, rp + 4);
}

// Guarded stage: OOB rows get -inf via direct STS (synchronous, own data).
__device__ __forceinline__ void stage_g(uint32_t wsm32, float* wsm, int lane,
                                        const float* __restrict__ fpr,
                                        int r, int g) {
    if ((unsigned)g < (unsigned)H_IN) {
        stage(wsm32, lane, fpr, r);
    } else {
        float4 ninf = make_float4(NEG_INF, NEG_INF, NEG_INF, NEG_INF);
        float4* q = (float4*)(wsm + (r & 7) * SLOT_F + lane * 8);
        q[0] = ninf; q[1] = ninf;
    }
}

// Read back this lane's 32B of a staged row.
__device__ __forceinline__ Row8 lrow(const float* wsm, int lane, int s) {
    const float4* q = (const float4*)(wsm + s * SLOT_F + lane * 8);
    Row8 x; x.a = q[0]; x.b = q[1]; return x;
}

// Horizontal 7-tap max-plus (symmetric weights): 4 output cols per lane.
__device__ __forceinline__ float4 hmax(const Row8& x, int lane,
                                       float h1, float h2, float h3)
{
    float m3 = __shfl_up_sync(0xffffffffu, x.b.y, 1);   // col 8l-3
    float m2 = __shfl_up_sync(0xffffffffu, x.b.z, 1);   // col 8l-2
    float m1 = __shfl_up_sync(0xffffffffu, x.b.w, 1);   // col 8l-1
    float p8 = __shfl_down_sync(0xffffffffu, x.a.x, 1); // col 8l+8
    float p9 = __shfl_down_sync(0xffffffffu, x.a.y, 1); // col 8l+9
    if (lane == 0)  { m3 = NEG_INF; m2 = NEG_INF; m1 = NEG_INF; }
    if (lane == 31) { p8 = NEG_INF; p9 = NEG_INF; }

    float4 g;
    g.x = fmaxf(fmaxf(x.a.x,                    fmaxf(m1,    x.a.y) + h1),
                fmaxf(fmaxf(m2,    x.a.z) + h2, fmaxf(m3,    x.a.w) + h3));
    g.y = fmaxf(fmaxf(x.a.z,                    fmaxf(x.a.y, x.a.w) + h1),
                fmaxf(fmaxf(x.a.x, x.b.x) + h2, fmaxf(m1,    x.b.y) + h3));
    g.z = fmaxf(fmaxf(x.b.x,                    fmaxf(x.a.w, x.b.y) + h1),
                fmaxf(fmaxf(x.a.z, x.b.z) + h2, fmaxf(x.a.y, x.b.w) + h3));
    g.w = fmaxf(fmaxf(x.b.z,                    fmaxf(x.b.y, x.b.w) + h1),
                fmaxf(fmaxf(x.b.x, p8)    + h2, fmaxf(x.a.w, p9)    + h3));
    return g;
}

__device__ __forceinline__ float4 vmax(const float4* ring, int s0,
                                       float h1, float h2, float h3)
{
    float4 c  = ring[s0 & 7];
    float4 a1 = ring[(s0 + 7) & 7], b1 = ring[(s0 + 1) & 7];
    float4 a2 = ring[(s0 + 6) & 7], b2 = ring[(s0 + 2) & 7];
    float4 a3 = ring[(s0 + 5) & 7], b3 = ring[(s0 + 3) & 7];
    float4 o;
    o.x = fmaxf(fmaxf(c.x, fmaxf(a1.x, b1.x) + h1),
                fmaxf(fmaxf(a2.x, b2.x) + h2, fmaxf(a3.x, b3.x) + h3));
    o.y = fmaxf(fmaxf(c.y, fmaxf(a1.y, b1.y) + h1),
                fmaxf(fmaxf(a2.y, b2.y) + h2, fmaxf(a3.y, b3.y) + h3));
    o.z = fmaxf(fmaxf(c.z, fmaxf(a1.z, b1.z) + h1),
                fmaxf(fmaxf(a2.z, b2.z) + h2, fmaxf(a3.z, b3.z) + h3));
    o.w = fmaxf(fmaxf(c.w, fmaxf(a1.w, b1.w) + h1),
                fmaxf(fmaxf(a2.w, b2.w) + h2, fmaxf(a3.w, b3.w) + h3));
    return o;
}

__global__ __launch_bounds__(32 * WARPS_PER_CTA)
void parabolic_pool_kernel(const float* __restrict__ f,
                           const float* __restrict__ tptr,
                           float* __restrict__ out)
{
    __shared__ __align__(16) float sbuf[WARPS_PER_CTA * WARP_F];  // 16 KB

    const int wid   = threadIdx.x >> 5;
    const int lane  = threadIdx.x & 31;
    const int gw    = blockIdx.x * WARPS_PER_CTA + wid;  // 0..4095
    const int plane = gw >> 1;
    const int i0    = (gw & 1) * 64;                     // output strip origin
    const int r0    = 2 * i0;                            // input row base

    float* wsm = &sbuf[wid * WARP_F];
    uint32_t wsm32 = (uint32_t)__cvta_generic_to_shared(wsm);

    // fpr: local row r -> global row r0 + r
    const float* __restrict__ fpr = f + (size_t)plane * (H_IN * W_IN)
                                      + (size_t)r0 * W_IN;
    float* __restrict__ op = out + (size_t)plane * (H_OUT * W_OUT)
                                 + (size_t)i0 * W_OUT + 4 * lane;

    const float inv4t = 0.25f / tptr[0];
    const float h1 = -1.0f * inv4t;
    const float h2 = -4.0f * inv4t;
    const float h3 = -9.0f * inv4t;

    float4 ring[8];   // ring[r & 7] = hmax of local input row r

    // ---- prologue: stage local rows -3..3 (guarded at top edge), one group ----
#pragma unroll
    for (int k = 0; k < 7; ++k) {
        const int r = k - 3;
        stage_g(wsm32, wsm, lane, fpr, r, r0 + r);
    }
    cp_commit();
    cp_wait<0>();
#pragma unroll
    for (int k = 0; k < 7; ++k) {
        const int r = k - 3;
        ring[r & 7] = hmax(lrow(wsm, lane, r & 7), lane, h1, h2, h3);
    }

    // prime 3 pairs in flight: rows (4,5), (6,7), (8,9) -- always in range
    stage(wsm32, lane, fpr, 4); stage(wsm32, lane, fpr, 5); cp_commit();
    stage(wsm32, lane, fpr, 6); stage(wsm32, lane, fpr, 7); cp_commit();
    stage(wsm32, lane, fpr, 8); stage(wsm32, lane, fpr, 9); cp_commit();

    // ---- body macro-step: commit (2i+10,2i+11); vmax+store i; wait; hmax (2i+4,2i+5)
#define BODY_STEP(i, ip)                                                      \
    {                                                                         \
        stage(wsm32, lane, fpr, 2*(i) + 10);                                  \
        stage(wsm32, lane, fpr, 2*(i) + 11);                                  \
        cp_commit();                                                          \
        float4 o = vmax(ring, (2*(ip)) & 7, h1, h2, h3);                      \
        __stcs((float4*)(op + (i) * W_OUT), o);                               \
        cp_wait<3>();                                                         \
        ring[(2*(ip)+4) & 7] = hmax(lrow(wsm, lane, (2*(ip)+4) & 7),          \
                                    lane, h1, h2, h3);                        \
        ring[(2*(ip)+5) & 7] = hmax(lrow(wsm, lane, (2*(ip)+5) & 7),          \
                                    lane, h1, h2, h3);                        \
    }

    // main loop: i = 0..55 (rows staged <= 121, always in range)
    for (int ib = 0; ib < 14; ++ib) {
#pragma unroll
        for (int ip = 0; ip < 4; ++ip) {
            const int i = ib * 4 + ip;
            BODY_STEP(i, ip);
        }
    }
    // i = 56..58: rows staged 122..127, in range for both strips
    BODY_STEP(56, 0);
    BODY_STEP(57, 1);
    BODY_STEP(58, 2);

    // i = 59: stage rows 128,129 (OOB for upper strip -> -inf via STS)
    {
        stage_g(wsm32, wsm, lane, fpr, 128, r0 + 128);
        stage_g(wsm32, wsm, lane, fpr, 129, r0 + 129);
        cp_commit();
        float4 o = vmax(ring, 6, h1, h2, h3);
        __stcs((float4*)(op + 59 * W_OUT), o);
        cp_wait<3>();
        ring[2] = hmax(lrow(wsm, lane, 2), lane, h1, h2, h3);   // row 122
        ring[3] = hmax(lrow(wsm, lane, 3), lane, h1, h2, h3);   // row 123
    }
    // i = 60..63: drain (no new commits)
    {
        float4 o = vmax(ring, 0, h1, h2, h3);
        __stcs((float4*)(op + 60 * W_OUT), o);
        cp_wait<2>();
        ring[4] = hmax(lrow(wsm, lane, 4), lane, h1, h2, h3);   // row 124
        ring[5] = hmax(lrow(wsm, lane, 5), lane, h1, h2, h3);   // row 125
    }
    {
        float4 o = vmax(ring, 2, h1, h2, h3);
        __stcs((float4*)(op + 61 * W_OUT), o);
        cp_wait<1>();
        ring[6] = hmax(lrow(wsm, lane, 6), lane, h1, h2, h3);   // row 126
        ring[7] = hmax(lrow(wsm, lane, 7), lane, h1, h2, h3);   // row 127
    }
    {
        float4 o = vmax(ring, 4, h1, h2, h3);
        __stcs((float4*)(op + 62 * W_OUT), o);
        cp_wait<0>();
        ring[0] = hmax(lrow(wsm, lane, 0), lane, h1, h2, h3);   // row 128
        ring[1] = hmax(lrow(wsm, lane, 1), lane, h1, h2, h3);   // row 129
    }
    {
        float4 o = vmax(ring, 6, h1, h2, h3);
        __stcs((float4*)(op + 63 * W_OUT), o);
    }
#undef BODY_STEP
}

extern "C" void kernel_launch(void* const* d_in, const int* in_sizes, int n_in,
                              void* d_out, int out_size)
{
    const float* f = (const float*)d_in[0];
    const float* t = (const float*)d_in[1];
    float* out = (float*)d_out;

    // 2048 planes x 2 row-strips = 4096 warps = 2048 blocks x 2 warps
    parabolic_pool_kernel<<<4096 / WARPS_PER_CTA, 32 * WARPS_PER_CTA>>>(f, t, out);
}